// round 3
// baseline (speedup 1.0000x reference)
#include <cuda_runtime.h>
#include <cstdint>

#define NIMG 8
#define AN   16384
#define CN   21
#define NCLS 20
#define TOPK 100
#define THR_PROB 0.05f
#define THR_NMS  0.45f
#define CAP  8192          // candidate capacity per (image,class); actual ~4800

// -------- device scratch (no allocations allowed) --------
__device__ float  g_scores[NIMG * NCLS * AN];   // thresholded per-class scores, -1 if inactive
__device__ float4 g_boxes [NIMG * AN];          // decoded clipped corner boxes
__device__ float  g_rows  [NIMG * NCLS * TOPK * 6];
__device__ int    g_counts[NIMG * NCLS];

// ---------------- stage 1: softmax + decode ----------------
__global__ void __launch_bounds__(256) k_prep(const float* __restrict__ cls,
                                              const float* __restrict__ reg,
                                              const float* __restrict__ anc) {
    int t = blockIdx.x * blockDim.x + threadIdx.x;
    if (t >= NIMG * AN) return;
    int a = t & (AN - 1);
    int n = t >> 14;

    const float* cp = cls + (size_t)t * CN;
    float x[CN];
    #pragma unroll
    for (int i = 0; i < CN; i++) x[i] = cp[i];
    float mx = x[0];
    #pragma unroll
    for (int i = 1; i < CN; i++) mx = fmaxf(mx, x[i]);
    float e[CN];
    float sum = 0.f;
    #pragma unroll
    for (int i = 0; i < CN; i++) { e[i] = expf(x[i] - mx); sum += e[i]; }
    #pragma unroll
    for (int c = 1; c < CN; c++) {
        float p = __fdiv_rn(e[c], sum);
        g_scores[(size_t)(n * NCLS + (c - 1)) * AN + a] = (p > THR_PROB) ? p : -1.0f;
    }

    float4 l   = ((const float4*)reg)[t];
    float4 an4 = ((const float4*)anc)[a];
    float cx = an4.x + l.x * 0.1f * an4.z;
    float cy = an4.y + l.y * 0.1f * an4.w;
    float w  = an4.z * expf(l.z * 0.2f);
    float h  = an4.w * expf(l.w * 0.2f);
    float hx = w * 0.5f, hy = h * 0.5f;
    float x1 = fminf(fmaxf(cx - hx, 0.f), 1.f);
    float y1 = fminf(fmaxf(cy - hy, 0.f), 1.f);
    float x2 = fminf(fmaxf(cx + hx, 0.f), 1.f);
    float y2 = fminf(fmaxf(cy + hy, 0.f), 1.f);
    g_boxes[t] = make_float4(x1, y1, x2, y2);
}

__device__ __forceinline__ bool iou_gt(float4 p, float4 q) {
    float areaP = (p.z - p.x) * (p.w - p.y);
    float areaQ = (q.z - q.x) * (q.w - q.y);
    float ltx = fmaxf(p.x, q.x), lty = fmaxf(p.y, q.y);
    float rbx = fminf(p.z, q.z), rby = fminf(p.w, q.w);
    float iw = fmaxf(rbx - ltx, 0.f), ih = fmaxf(rby - lty, 0.f);
    float inter = iw * ih;
    float uni = areaP + areaQ - inter;
    float iou = (uni > 0.f) ? __fdiv_rn(inter, uni) : 0.f;
    return iou > THR_NMS;
}

// ---------------- stage 2: per-(image,class) sorted-greedy NMS ----------------
// Dynamic smem: 64-bit keys[CAP]. key = (score_bits << 14) | (16383 - anchor).
// Full total order: higher score first, ties broken by lower anchor index —
// identical semantics to repeated argmax in the reference.
#define SMEM_NMS (CAP * 8)

__global__ void __launch_bounds__(256) k_nms() {
    extern __shared__ uint64_t keys[];
    __shared__ int s_cnt;

    const int tid  = threadIdx.x;
    const int lane = tid & 31;
    const int wid  = tid >> 5;
    const int n    = blockIdx.x / NCLS;
    const int cc   = blockIdx.x % NCLS;           // class = cc+1
    const float*  sc   = g_scores + (size_t)(n * NCLS + cc) * AN;
    const float4* boxN = g_boxes + (size_t)n * AN;
    float* rowBase = g_rows + (size_t)(n * NCLS + cc) * TOPK * 6;
    const unsigned FULL = 0xFFFFFFFFu;

    if (tid == 0) s_cnt = 0;
    __syncthreads();

    // compaction: one warp-aggregated atomic per iteration
    for (int base = wid * 32; base < AN; base += 256) {
        int a = base + lane;
        float s = sc[a];
        bool pass = (s > 0.f);
        unsigned bal = __ballot_sync(FULL, pass);
        int cntw = __popc(bal);
        int pos = 0;
        if (lane == 0 && cntw) pos = atomicAdd(&s_cnt, cntw);
        pos = __shfl_sync(FULL, pos, 0);
        if (pass) {
            int my = pos + __popc(bal & ((1u << lane) - 1));
            if (my < CAP)
                keys[my] = ((uint64_t)__float_as_uint(s) << 14) | (uint64_t)(16383 - a);
        }
    }
    __syncthreads();

    int cnt = s_cnt;
    if (cnt > CAP) cnt = CAP;

    // pad to power of two
    int P = 32;
    while (P < cnt) P <<= 1;
    for (int i = cnt + tid; i < P; i += 256) keys[i] = 0ull;
    __syncthreads();

    // block bitonic sort, descending
    for (int k = 2; k <= P; k <<= 1)
        for (int j = k >> 1; j > 0; j >>= 1) {
            for (int i = tid; i < (P >> 1); i += 256) {
                int pos = ((i & ~(j - 1)) << 1) | (i & (j - 1));
                int par = pos | j;
                uint64_t xv = keys[pos], yv = keys[par];
                bool desc = ((pos & k) == 0);
                if (desc ? (xv < yv) : (xv > yv)) { keys[pos] = yv; keys[par] = xv; }
            }
            __syncthreads();
        }

    // ---- greedy walk (warp 0 only): candidates already in exact order ----
    if (wid != 0) return;

    float4 sel0, sel1, sel2, sel3;      // selected boxes: slot s holds idx s*32+lane
    int selcnt = 0;

    for (int base = 0; base < cnt && selcnt < TOPK; base += 32) {
        int m = min(32, cnt - base);
        uint64_t key = (lane < m) ? keys[base + lane] : 0ull;
        float4 myb = make_float4(0.f, 0.f, 0.f, 0.f);
        if (lane < m) myb = boxN[16383u - ((uint32_t)key & 0x3FFFu)];

        for (int t = 0; t < m && selcnt < TOPK; t++) {
            float4 cb;
            cb.x = __shfl_sync(FULL, myb.x, t);
            cb.y = __shfl_sync(FULL, myb.y, t);
            cb.z = __shfl_sync(FULL, myb.z, t);
            cb.w = __shfl_sync(FULL, myb.w, t);

            bool sup = false;
            if (lane      < selcnt) sup |= iou_gt(sel0, cb);
            if (lane + 32 < selcnt) sup |= iou_gt(sel1, cb);
            if (lane + 64 < selcnt) sup |= iou_gt(sel2, cb);
            if (lane + 96 < selcnt) sup |= iou_gt(sel3, cb);

            if (!__any_sync(FULL, sup)) {
                int slot = selcnt >> 5, ln = selcnt & 31;
                if (lane == ln) {
                    if      (slot == 0) sel0 = cb;
                    else if (slot == 1) sel1 = cb;
                    else if (slot == 2) sel2 = cb;
                    else                sel3 = cb;
                }
                if (lane == t) {   // this lane owns the key -> has score bits
                    float* r = rowBase + selcnt * 6;
                    r[0] = cb.x; r[1] = cb.y; r[2] = cb.z; r[3] = cb.w;
                    r[4] = __uint_as_float((uint32_t)(key >> 14));
                    r[5] = (float)(cc + 1);
                }
                selcnt++;
            }
        }
    }
    if (lane == 0) g_counts[n * NCLS + cc] = selcnt;
}

// ---------------- stage 3: per-image top-100 (lax.top_k semantics) ----------------
__global__ void __launch_bounds__(256) k_topk(float* __restrict__ out) {
    __shared__ uint64_t kb[2048];
    const int n = blockIdx.x, tid = threadIdx.x;

    for (int e = tid; e < 2048; e += 256) {
        uint64_t key = 0ull;
        if (e < NCLS * TOPK) {
            int c = e / TOPK, k = e % TOPK;
            if (k < g_counts[n * NCLS + c]) {
                float s = g_rows[(((size_t)(n * NCLS + c)) * TOPK + k) * 6 + 4];
                uint32_t flat = (uint32_t)((c + 1) * TOPK + k);   // flat idx in [N, C*TOPK] layout
                key = ((uint64_t)__float_as_uint(s) << 32) | (uint64_t)(4095u - flat);
            }
        }
        kb[e] = key;
    }
    __syncthreads();

    for (int k = 2; k <= 2048; k <<= 1)
        for (int j = k >> 1; j > 0; j >>= 1) {
            for (int i = tid; i < 1024; i += 256) {
                int pos = ((i & ~(j - 1)) << 1) | (i & (j - 1));
                int par = pos | j;
                uint64_t xv = kb[pos], yv = kb[par];
                bool desc = ((pos & k) == 0);
                if (desc ? (xv < yv) : (xv > yv)) { kb[pos] = yv; kb[par] = xv; }
            }
            __syncthreads();
        }

    if (tid < TOPK) {
        uint64_t key = kb[tid];
        float* o = out + ((size_t)n * TOPK + tid) * 6;
        if ((key >> 32) != 0ull) {
            uint32_t flat = 4095u - (uint32_t)key;
            int c = (int)(flat / TOPK) - 1;
            int k = (int)(flat % TOPK);
            const float* r = g_rows + (((size_t)(n * NCLS + c)) * TOPK + k) * 6;
            #pragma unroll
            for (int j = 0; j < 6; j++) o[j] = r[j];
        } else {
            #pragma unroll
            for (int j = 0; j < 6; j++) o[j] = 0.f;
        }
    }
}

extern "C" void kernel_launch(void* const* d_in, const int* in_sizes, int n_in,
                              void* d_out, int out_size) {
    (void)in_sizes; (void)n_in; (void)out_size;
    const float* cls = (const float*)d_in[0];
    const float* reg = (const float*)d_in[1];
    const float* anc = (const float*)d_in[2];
    float* out = (float*)d_out;

    cudaFuncSetAttribute(k_nms, cudaFuncAttributeMaxDynamicSharedMemorySize, SMEM_NMS);

    k_prep<<<(NIMG * AN) / 256, 256>>>(cls, reg, anc);
    k_nms <<<NIMG * NCLS, 256, SMEM_NMS>>>();
    k_topk<<<NIMG, 256>>>(out);
}

// round 4
// speedup vs baseline: 1.6708x; 1.6708x over previous
#include <cuda_runtime.h>
#include <cstdint>

#define NIMG 8
#define AN   16384
#define CN   21
#define NCLS 20
#define TOPK 100
#define NB   564            // buckets: (score_bits>>16) - 0x3D4C, scores in (0.05, 1)
#define BBASE 0x3D4Cu
#define THR_PROB 0.05f
#define THR_NMS  0.45f
#define CAP   8192          // per-(n,c) candidate capacity (actual ~4800, sigma ~42)
#define CAP2  2048          // per-chunk capacity
#define CHUNK 384

// -------- device scratch (no allocations allowed) --------
__device__ float4   g_boxes [NIMG * AN];
__device__ uint64_t g_cands [NIMG * NCLS * CAP];   // key = score_bits<<14 | (16383-anchor)
__device__ int      g_cnt   [NIMG * NCLS];          // zero-init; reset by k_nms each run
__device__ float    g_rows  [NIMG * NCLS * TOPK * 6];
__device__ int      g_counts[NIMG * NCLS];

// ---------------- stage 1: softmax + decode + direct candidate push ----------------
__global__ void __launch_bounds__(256) k_prep(const float* __restrict__ cls,
                                              const float* __restrict__ reg,
                                              const float* __restrict__ anc) {
    const unsigned FULL = 0xFFFFFFFFu;
    int t = blockIdx.x * blockDim.x + threadIdx.x;   // grid exact: NIMG*AN threads
    int a = t & (AN - 1);
    int n = t >> 14;
    int lane = threadIdx.x & 31;

    const float* cp = cls + (size_t)t * CN;
    float x[CN];
    #pragma unroll
    for (int i = 0; i < CN; i++) x[i] = cp[i];
    float mx = x[0];
    #pragma unroll
    for (int i = 1; i < CN; i++) mx = fmaxf(mx, x[i]);
    float e[CN];
    float sum = 0.f;
    #pragma unroll
    for (int i = 0; i < CN; i++) { e[i] = expf(x[i] - mx); sum += e[i]; }

    #pragma unroll
    for (int c = 1; c < CN; c++) {
        float p = __fdiv_rn(e[c], sum);
        bool pass = (p > THR_PROB);
        unsigned bal = __ballot_sync(FULL, pass);
        if (bal) {
            int nc = n * NCLS + (c - 1);
            int pos = 0;
            if (lane == 0) pos = atomicAdd(&g_cnt[nc], __popc(bal));
            pos = __shfl_sync(FULL, pos, 0);
            if (pass) {
                int my = pos + __popc(bal & ((1u << lane) - 1));
                if (my < CAP)
                    g_cands[(size_t)nc * CAP + my] =
                        ((uint64_t)__float_as_uint(p) << 14) | (uint64_t)(16383 - a);
            }
        }
    }

    float4 l   = ((const float4*)reg)[t];
    float4 an4 = ((const float4*)anc)[a];
    float cx = an4.x + l.x * 0.1f * an4.z;
    float cy = an4.y + l.y * 0.1f * an4.w;
    float w  = an4.z * expf(l.z * 0.2f);
    float h  = an4.w * expf(l.w * 0.2f);
    float hx = w * 0.5f, hy = h * 0.5f;
    float x1 = fminf(fmaxf(cx - hx, 0.f), 1.f);
    float y1 = fminf(fmaxf(cy - hy, 0.f), 1.f);
    float x2 = fminf(fmaxf(cx + hx, 0.f), 1.f);
    float y2 = fminf(fmaxf(cy + hy, 0.f), 1.f);
    g_boxes[t] = make_float4(x1, y1, x2, y2);
}

// IoU check with pre-hoisted areas; exact same op order as reference
__device__ __forceinline__ bool iou_gt2(float4 p, float aP, float4 q, float aQ) {
    float ltx = fmaxf(p.x, q.x), lty = fmaxf(p.y, q.y);
    float rbx = fminf(p.z, q.z), rby = fminf(p.w, q.w);
    float iw = fmaxf(rbx - ltx, 0.f), ih = fmaxf(rby - lty, 0.f);
    float inter = iw * ih;
    float uni = aP + aQ - inter;
    float iou = (uni > 0.f) ? __fdiv_rn(inter, uni) : 0.f;
    return iou > THR_NMS;
}

// ---------------- stage 2: per-(image,class) threshold + small-sort greedy NMS ----------------
__global__ void __launch_bounds__(256) k_nms() {
    __shared__ uint64_t keys2[CAP2];          // 16 KB
    __shared__ uint32_t whist[8][576];        // 18 KB per-warp histograms
    __shared__ uint32_t hist[577];
    __shared__ uint32_t sufc[577];            // suffix counts: sufc[b] = #cands in buckets >= b
    __shared__ int s_blo, s_cnt2, s_selcnt;

    const unsigned FULL = 0xFFFFFFFFu;
    const int tid  = threadIdx.x;
    const int lane = tid & 31;
    const int wid  = tid >> 5;
    const int n    = blockIdx.x / NCLS;
    const int cc   = blockIdx.x % NCLS;
    const int nc   = n * NCLS + cc;
    const uint64_t* glist = g_cands + (size_t)nc * CAP;
    const float4*   boxN  = g_boxes + (size_t)n * AN;
    float* rowBase = g_rows + (size_t)nc * TOPK * 6;

    int cnt = g_cnt[nc];
    if (cnt > CAP) cnt = CAP;

    for (int i = tid; i < 8 * 576; i += 256) ((uint32_t*)whist)[i] = 0;
    if (tid == 0) s_selcnt = 0;
    __syncthreads();

    // per-warp histogram over candidate buckets
    for (int i = tid; i < cnt; i += 256) {
        uint64_t key = glist[i];
        int b = (int)(uint32_t)(key >> 30) - (int)BBASE;
        atomicAdd(&whist[wid][b], 1u);
    }
    __syncthreads();

    for (int b = tid; b < 576; b += 256) {
        uint32_t s = 0;
        #pragma unroll
        for (int w = 0; w < 8; w++) s += whist[w][b];
        hist[b] = s;
    }
    __syncthreads();

    // suffix sums (warp 0): lane handles reversed segment of 18 buckets
    if (tid < 32) {
        int hi = 576 - 18 * lane;    // exclusive
        int lo = hi - 18;
        uint32_t sum = 0;
        #pragma unroll
        for (int b = 0; b < 18; b++) sum += hist[lo + b];
        uint32_t pre = sum;
        #pragma unroll
        for (int d = 1; d < 32; d <<= 1) {
            uint32_t v = __shfl_up_sync(FULL, pre, d);
            if (lane >= d) pre += v;
        }
        uint32_t run = pre - sum;    // count in buckets >= hi
        for (int b = hi - 1; b >= lo; b--) { run += hist[b]; sufc[b] = run; }
        if (lane == 0) sufc[576] = 0;
    }
    __syncthreads();

    // greedy state persists in warp 0's registers across chunks
    float4 sel0, sel1, sel2, sel3;
    float  aS0 = 0.f, aS1 = 0.f, aS2 = 0.f, aS3 = 0.f;
    int selcnt = 0;

    int b_hi = NB - 1;
    while (true) {
        // pick cutoff bucket capturing the next ~CHUNK candidates
        if (tid == 0) {
            uint32_t consumed = sufc[b_hi + 1];
            uint32_t target = consumed + CHUNK;
            int blo = 0;
            if (sufc[0] >= target) {
                int lo2 = 0, hi2 = b_hi;
                while (lo2 < hi2) {            // largest b with sufc[b] >= target
                    int mid = (lo2 + hi2 + 1) >> 1;
                    if (sufc[mid] >= target) lo2 = mid; else hi2 = mid - 1;
                }
                blo = lo2;
            }
            s_blo = blo;
            s_cnt2 = 0;
        }
        __syncthreads();
        const int blo = s_blo;

        // compact candidates in bucket range [blo, b_hi] into keys2
        for (int base = wid * 32; base < cnt; base += 256) {
            int i = base + lane;
            uint64_t key = 0ull;
            bool sel = false;
            if (i < cnt) {
                key = glist[i];
                int b = (int)(uint32_t)(key >> 30) - (int)BBASE;
                sel = (b >= blo) && (b <= b_hi);
            }
            unsigned bal = __ballot_sync(FULL, sel);
            if (bal) {
                int pos = 0;
                if (lane == 0) pos = atomicAdd(&s_cnt2, __popc(bal));
                pos = __shfl_sync(FULL, pos, 0);
                if (sel) {
                    int my = pos + __popc(bal & ((1u << lane) - 1));
                    if (my < CAP2) keys2[my] = key;
                }
            }
        }
        __syncthreads();
        int M = s_cnt2;
        if (M > CAP2) M = CAP2;

        // pad + bitonic sort descending (small: P typically 512)
        int P = 32;
        while (P < M) P <<= 1;
        for (int i = M + tid; i < P; i += 256) keys2[i] = 0ull;
        __syncthreads();
        for (int k = 2; k <= P; k <<= 1)
            for (int j = k >> 1; j > 0; j >>= 1) {
                for (int i = tid; i < (P >> 1); i += 256) {
                    int pos = ((i & ~(j - 1)) << 1) | (i & (j - 1));
                    int par = pos | j;
                    uint64_t xv = keys2[pos], yv = keys2[par];
                    bool desc = ((pos & k) == 0);
                    if (desc ? (xv < yv) : (xv > yv)) { keys2[pos] = yv; keys2[par] = xv; }
                }
                __syncthreads();
            }

        // greedy walk (warp 0), 32-wide box prefetch
        if (wid == 0) {
            for (int base = 0; base < M && selcnt < TOPK; base += 32) {
                int m = min(32, M - base);
                uint64_t key = (lane < m) ? keys2[base + lane] : 0ull;
                float4 myb = make_float4(0.f, 0.f, 0.f, 0.f);
                if (lane < m) myb = boxN[16383u - ((uint32_t)key & 0x3FFFu)];
                float myA = (myb.z - myb.x) * (myb.w - myb.y);

                for (int t = 0; t < m && selcnt < TOPK; t++) {
                    float4 cb;
                    cb.x = __shfl_sync(FULL, myb.x, t);
                    cb.y = __shfl_sync(FULL, myb.y, t);
                    cb.z = __shfl_sync(FULL, myb.z, t);
                    cb.w = __shfl_sync(FULL, myb.w, t);
                    float aQ = __shfl_sync(FULL, myA, t);

                    bool sup = false;
                    if (lane      < selcnt) sup |= iou_gt2(sel0, aS0, cb, aQ);
                    if (lane + 32 < selcnt) sup |= iou_gt2(sel1, aS1, cb, aQ);
                    if (lane + 64 < selcnt) sup |= iou_gt2(sel2, aS2, cb, aQ);
                    if (lane + 96 < selcnt) sup |= iou_gt2(sel3, aS3, cb, aQ);

                    if (!__any_sync(FULL, sup)) {
                        int slot = selcnt >> 5, ln = selcnt & 31;
                        if (lane == ln) {
                            if      (slot == 0) { sel0 = cb; aS0 = aQ; }
                            else if (slot == 1) { sel1 = cb; aS1 = aQ; }
                            else if (slot == 2) { sel2 = cb; aS2 = aQ; }
                            else                { sel3 = cb; aS3 = aQ; }
                        }
                        if (lane == t) {
                            float* r = rowBase + selcnt * 6;
                            r[0] = cb.x; r[1] = cb.y; r[2] = cb.z; r[3] = cb.w;
                            r[4] = __uint_as_float((uint32_t)(key >> 14));
                            r[5] = (float)(cc + 1);
                        }
                        selcnt++;
                    }
                }
            }
            if (lane == 0) s_selcnt = selcnt;
        }
        __syncthreads();

        bool done = (s_selcnt >= TOPK) || (blo == 0);
        if (done) {
            if (tid == 0) { g_counts[nc] = s_selcnt; g_cnt[nc] = 0; }  // reset for next replay
            break;
        }
        b_hi = blo - 1;
    }
}

// ---------------- stage 3: per-image top-100 (lax.top_k semantics) ----------------
__global__ void __launch_bounds__(256) k_topk(float* __restrict__ out) {
    __shared__ uint64_t kb[2048];
    const int n = blockIdx.x, tid = threadIdx.x;

    for (int e = tid; e < 2048; e += 256) {
        uint64_t key = 0ull;
        if (e < NCLS * TOPK) {
            int c = e / TOPK, k = e % TOPK;
            if (k < g_counts[n * NCLS + c]) {
                float s = g_rows[(((size_t)(n * NCLS + c)) * TOPK + k) * 6 + 4];
                uint32_t flat = (uint32_t)((c + 1) * TOPK + k);
                key = ((uint64_t)__float_as_uint(s) << 32) | (uint64_t)(4095u - flat);
            }
        }
        kb[e] = key;
    }
    __syncthreads();

    for (int k = 2; k <= 2048; k <<= 1)
        for (int j = k >> 1; j > 0; j >>= 1) {
            for (int i = tid; i < 1024; i += 256) {
                int pos = ((i & ~(j - 1)) << 1) | (i & (j - 1));
                int par = pos | j;
                uint64_t xv = kb[pos], yv = kb[par];
                bool desc = ((pos & k) == 0);
                if (desc ? (xv < yv) : (xv > yv)) { kb[pos] = yv; kb[par] = xv; }
            }
            __syncthreads();
        }

    if (tid < TOPK) {
        uint64_t key = kb[tid];
        float* o = out + ((size_t)n * TOPK + tid) * 6;
        if ((key >> 32) != 0ull) {
            uint32_t flat = 4095u - (uint32_t)key;
            int c = (int)(flat / TOPK) - 1;
            int k = (int)(flat % TOPK);
            const float* r = g_rows + (((size_t)(n * NCLS + c)) * TOPK + k) * 6;
            #pragma unroll
            for (int j = 0; j < 6; j++) o[j] = r[j];
        } else {
            #pragma unroll
            for (int j = 0; j < 6; j++) o[j] = 0.f;
        }
    }
}

extern "C" void kernel_launch(void* const* d_in, const int* in_sizes, int n_in,
                              void* d_out, int out_size) {
    (void)in_sizes; (void)n_in; (void)out_size;
    const float* cls = (const float*)d_in[0];
    const float* reg = (const float*)d_in[1];
    const float* anc = (const float*)d_in[2];
    float* out = (float*)d_out;

    k_prep<<<(NIMG * AN) / 256, 256>>>(cls, reg, anc);
    k_nms <<<NIMG * NCLS, 256>>>();
    k_topk<<<NIMG, 256>>>(out);
}

// round 5
// speedup vs baseline: 2.0100x; 1.2030x over previous
#include <cuda_runtime.h>
#include <cstdint>

#define NIMG 8
#define AN   16384
#define CN   21
#define NCLS 20
#define TOPK 100
#define NB   564            // buckets: (score_bits>>16) - 0x3D4C, scores in (0.05, 1)
#define BBASE 0x3D4Cu
#define THR_PROB 0.05f
#define THR_NMS  0.45f
#define CAP   8192          // per-(n,c) candidate capacity (actual ~4800, sigma ~42)
#define CAP2  1024          // per-chunk capacity
#define CHUNK 512

// -------- device scratch (no allocations allowed) --------
__device__ float4   g_boxes [NIMG * AN];
__device__ uint64_t g_cands [NIMG * NCLS * CAP];   // key = score_bits<<14 | (16383-anchor)
__device__ int      g_cnt   [NIMG * NCLS];          // zero-init; reset by k_nms each run
__device__ float    g_rows  [NIMG * NCLS * TOPK * 6];
__device__ int      g_counts[NIMG * NCLS];

// ---------------- stage 1: softmax + decode + direct candidate push ----------------
__global__ void __launch_bounds__(256) k_prep(const float* __restrict__ cls,
                                              const float* __restrict__ reg,
                                              const float* __restrict__ anc) {
    __shared__ float tile[8][672];   // 21 KB: per-warp staging of 32 anchors x 21 logits
    const unsigned FULL = 0xFFFFFFFFu;
    const int tid  = threadIdx.x;
    const int lane = tid & 31;
    const int wid  = tid >> 5;
    int t = blockIdx.x * blockDim.x + tid;           // grid exact: NIMG*AN threads
    int a = t & (AN - 1);
    int n = t >> 14;

    // coalesced float4 staging: 672 floats = 168 float4 per warp
    {
        const float4* src = (const float4*)(cls + (size_t)(t - lane) * CN);
        float4* dst = (float4*)tile[wid];
        #pragma unroll
        for (int i = 0; i < 5; i++) dst[lane + 32 * i] = src[lane + 32 * i];
        if (lane < 8) dst[lane + 160] = src[lane + 160];
        __syncwarp();
    }

    float x[CN];
    #pragma unroll
    for (int i = 0; i < CN; i++) x[i] = tile[wid][lane * CN + i];

    float mx = x[0];
    #pragma unroll
    for (int i = 1; i < CN; i++) mx = fmaxf(mx, x[i]);
    float e[CN];
    float sum = 0.f;
    #pragma unroll
    for (int i = 0; i < CN; i++) { e[i] = expf(x[i] - mx); sum += e[i]; }

    // pass 1: probabilities + per-class ballots; lane c-1 keeps ballot of class c
    unsigned myBal = 0;
    #pragma unroll
    for (int c = 1; c < CN; c++) {
        float p = __fdiv_rn(e[c], sum);
        e[c] = p;
        unsigned b = __ballot_sync(FULL, p > THR_PROB);
        if (lane == c - 1) myBal = b;
    }
    // single warp-wide atomic: lane c updates class-c counter (spread addrs, one latency)
    int basePos = 0;
    if (lane < NCLS) basePos = atomicAdd(&g_cnt[n * NCLS + lane], __popc(myBal));

    // pass 2: positions + key stores
    #pragma unroll
    for (int c = 1; c < CN; c++) {
        float p = e[c];
        bool pass = (p > THR_PROB);
        unsigned b = __ballot_sync(FULL, pass);
        int pos = __shfl_sync(FULL, basePos, c - 1);
        if (pass) {
            int my = pos + __popc(b & ((1u << lane) - 1));
            if (my < CAP)
                g_cands[(size_t)(n * NCLS + (c - 1)) * CAP + my] =
                    ((uint64_t)__float_as_uint(p) << 14) | (uint64_t)(16383 - a);
        }
    }

    float4 l   = ((const float4*)reg)[t];
    float4 an4 = ((const float4*)anc)[a];
    float cx = an4.x + l.x * 0.1f * an4.z;
    float cy = an4.y + l.y * 0.1f * an4.w;
    float w  = an4.z * expf(l.z * 0.2f);
    float h  = an4.w * expf(l.w * 0.2f);
    float hx = w * 0.5f, hy = h * 0.5f;
    float x1 = fminf(fmaxf(cx - hx, 0.f), 1.f);
    float y1 = fminf(fmaxf(cy - hy, 0.f), 1.f);
    float x2 = fminf(fmaxf(cx + hx, 0.f), 1.f);
    float y2 = fminf(fmaxf(cy + hy, 0.f), 1.f);
    g_boxes[t] = make_float4(x1, y1, x2, y2);
}

// IoU check with pre-hoisted areas; exact same op order as reference
__device__ __forceinline__ bool iou_gt2(float4 p, float aP, float4 q, float aQ) {
    float ltx = fmaxf(p.x, q.x), lty = fmaxf(p.y, q.y);
    float rbx = fminf(p.z, q.z), rby = fminf(p.w, q.w);
    float iw = fmaxf(rbx - ltx, 0.f), ih = fmaxf(rby - lty, 0.f);
    float inter = iw * ih;
    float uni = aP + aQ - inter;
    float iou = (uni > 0.f) ? __fdiv_rn(inter, uni) : 0.f;
    return iou > THR_NMS;
}

// ---------------- stage 2: per-(image,class) threshold + small-sort greedy NMS ----------------
__global__ void __launch_bounds__(256) k_nms() {
    __shared__ uint64_t keys2[CAP2];          // 8 KB
    __shared__ uint32_t whist[8][576];        // 18 KB
    __shared__ uint32_t hist[577];
    __shared__ uint32_t sufc[577];            // sufc[b] = #cands in buckets >= b
    __shared__ float4   s_selbox[TOPK];
    __shared__ float    s_selA[TOPK];
    __shared__ float4   s_wbox[32];
    __shared__ float    s_wA[32];
    __shared__ int s_blo, s_cnt2, s_selcnt;

    const unsigned FULL = 0xFFFFFFFFu;
    const int tid  = threadIdx.x;
    const int lane = tid & 31;
    const int wid  = tid >> 5;
    const int n    = blockIdx.x / NCLS;
    const int cc   = blockIdx.x % NCLS;
    const int nc   = n * NCLS + cc;
    const uint64_t* glist = g_cands + (size_t)nc * CAP;
    const float4*   boxN  = g_boxes + (size_t)n * AN;
    float* rowBase = g_rows + (size_t)nc * TOPK * 6;

    int cnt = g_cnt[nc];
    if (cnt > CAP) cnt = CAP;

    for (int i = tid; i < 8 * 576; i += 256) ((uint32_t*)whist)[i] = 0;
    if (tid == 0) s_selcnt = 0;
    __syncthreads();

    for (int i = tid; i < cnt; i += 256) {
        uint64_t key = glist[i];
        int b = (int)(uint32_t)(key >> 30) - (int)BBASE;
        atomicAdd(&whist[wid][b], 1u);
    }
    __syncthreads();

    for (int b = tid; b < 576; b += 256) {
        uint32_t s = 0;
        #pragma unroll
        for (int w = 0; w < 8; w++) s += whist[w][b];
        hist[b] = s;
    }
    __syncthreads();

    if (tid < 32) {
        int hi = 576 - 18 * lane;
        int lo = hi - 18;
        uint32_t sum = 0;
        #pragma unroll
        for (int b = 0; b < 18; b++) sum += hist[lo + b];
        uint32_t pre = sum;
        #pragma unroll
        for (int d = 1; d < 32; d <<= 1) {
            uint32_t v = __shfl_up_sync(FULL, pre, d);
            if (lane >= d) pre += v;
        }
        uint32_t run = pre - sum;
        for (int b = hi - 1; b >= lo; b--) { run += hist[b]; sufc[b] = run; }
        if (lane == 0) sufc[576] = 0;
    }
    __syncthreads();

    int b_hi = NB - 1;
    while (true) {
        if (tid == 0) {
            uint32_t target = sufc[b_hi + 1] + CHUNK;
            int blo = 0;
            if (sufc[0] >= target) {
                int lo2 = 0, hi2 = b_hi;
                while (lo2 < hi2) {
                    int mid = (lo2 + hi2 + 1) >> 1;
                    if (sufc[mid] >= target) lo2 = mid; else hi2 = mid - 1;
                }
                blo = lo2;
            }
            s_blo = blo;
            s_cnt2 = 0;
        }
        __syncthreads();
        const int blo = s_blo;

        for (int base = wid * 32; base < cnt; base += 256) {
            int i = base + lane;
            uint64_t key = 0ull;
            bool sel = false;
            if (i < cnt) {
                key = glist[i];
                int b = (int)(uint32_t)(key >> 30) - (int)BBASE;
                sel = (b >= blo) && (b <= b_hi);
            }
            unsigned bal = __ballot_sync(FULL, sel);
            if (bal) {
                int pos = 0;
                if (lane == 0) pos = atomicAdd(&s_cnt2, __popc(bal));
                pos = __shfl_sync(FULL, pos, 0);
                if (sel) {
                    int my = pos + __popc(bal & ((1u << lane) - 1));
                    if (my < CAP2) keys2[my] = key;
                }
            }
        }
        __syncthreads();
        int M = s_cnt2;
        if (M > CAP2) M = CAP2;

        int P = 32;
        while (P < M) P <<= 1;
        for (int i = M + tid; i < P; i += 256) keys2[i] = 0ull;
        __syncthreads();
        for (int k = 2; k <= P; k <<= 1)
            for (int j = k >> 1; j > 0; j >>= 1) {
                for (int i = tid; i < (P >> 1); i += 256) {
                    int pos = ((i & ~(j - 1)) << 1) | (i & (j - 1));
                    int par = pos | j;
                    uint64_t xv = keys2[pos], yv = keys2[par];
                    bool desc = ((pos & k) == 0);
                    if (desc ? (xv < yv) : (xv > yv)) { keys2[pos] = yv; keys2[par] = xv; }
                }
                __syncthreads();
            }

        // ---- batch-32 greedy walk (warp 0): exact sequential-greedy semantics ----
        if (wid == 0) {
            int selcnt = s_selcnt;
            for (int base = 0; base < M && selcnt < TOPK; base += 32) {
                int m = min(32, M - base);
                uint64_t key = (lane < m) ? keys2[base + lane] : 0ull;
                float4 myb = make_float4(0.f, 0.f, 0.f, 0.f);
                if (lane < m) myb = boxN[16383u - ((uint32_t)key & 0x3FFFu)];
                float myA = (myb.z - myb.x) * (myb.w - myb.y);
                s_wbox[lane] = myb;
                s_wA[lane] = myA;
                __syncwarp(FULL);

                bool sup = (lane >= m);
                for (int j = 0; j < selcnt; j++)
                    sup |= iou_gt2(s_selbox[j], s_selA[j], myb, myA);
                unsigned supb = __ballot_sync(FULL, sup);
                if (supb == FULL) continue;

                unsigned mymask = 0;
                #pragma unroll 8
                for (int j = 0; j < 32; j++) {
                    if (j < lane && j < m) {
                        if (iou_gt2(s_wbox[j], s_wA[j], myb, myA)) mymask |= 1u << j;
                    }
                }

                unsigned killed = supb;
                unsigned selMask = 0;
                int space = TOPK - selcnt;
                for (int i = 0; i < m; i++) {
                    if (space == 0) break;
                    if (!((killed >> i) & 1)) {
                        selMask |= 1u << i;
                        space--;
                        killed |= __ballot_sync(FULL, (mymask >> i) & 1);
                    }
                }

                bool selme = (selMask >> lane) & 1;
                int rank = __popc(selMask & ((1u << lane) - 1));
                if (selme) {
                    int slot = selcnt + rank;
                    s_selbox[slot] = myb;
                    s_selA[slot] = myA;
                    float* r = rowBase + slot * 6;
                    r[0] = myb.x; r[1] = myb.y; r[2] = myb.z; r[3] = myb.w;
                    r[4] = __uint_as_float((uint32_t)(key >> 14));
                    r[5] = (float)(cc + 1);
                }
                selcnt += __popc(selMask);
                __syncwarp(FULL);
            }
            if (lane == 0) s_selcnt = selcnt;
        }
        __syncthreads();

        if (s_selcnt >= TOPK || blo == 0) {
            if (tid == 0) { g_counts[nc] = s_selcnt; g_cnt[nc] = 0; }
            break;
        }
        b_hi = blo - 1;
    }
}

// ---------------- stage 3: per-image top-100 (lax.top_k semantics) ----------------
__global__ void __launch_bounds__(256) k_topk(float* __restrict__ out) {
    __shared__ uint64_t kb[2048];
    const int n = blockIdx.x, tid = threadIdx.x;

    for (int e = tid; e < 2048; e += 256) {
        uint64_t key = 0ull;
        if (e < NCLS * TOPK) {
            int c = e / TOPK, k = e % TOPK;
            if (k < g_counts[n * NCLS + c]) {
                float s = g_rows[(((size_t)(n * NCLS + c)) * TOPK + k) * 6 + 4];
                uint32_t flat = (uint32_t)((c + 1) * TOPK + k);
                key = ((uint64_t)__float_as_uint(s) << 32) | (uint64_t)(4095u - flat);
            }
        }
        kb[e] = key;
    }
    __syncthreads();

    for (int k = 2; k <= 2048; k <<= 1)
        for (int j = k >> 1; j > 0; j >>= 1) {
            for (int i = tid; i < 1024; i += 256) {
                int pos = ((i & ~(j - 1)) << 1) | (i & (j - 1));
                int par = pos | j;
                uint64_t xv = kb[pos], yv = kb[par];
                bool desc = ((pos & k) == 0);
                if (desc ? (xv < yv) : (xv > yv)) { kb[pos] = yv; kb[par] = xv; }
            }
            __syncthreads();
        }

    if (tid < TOPK) {
        uint64_t key = kb[tid];
        float* o = out + ((size_t)n * TOPK + tid) * 6;
        if ((key >> 32) != 0ull) {
            uint32_t flat = 4095u - (uint32_t)key;
            int c = (int)(flat / TOPK) - 1;
            int k = (int)(flat % TOPK);
            const float* r = g_rows + (((size_t)(n * NCLS + c)) * TOPK + k) * 6;
            #pragma unroll
            for (int j = 0; j < 6; j++) o[j] = r[j];
        } else {
            #pragma unroll
            for (int j = 0; j < 6; j++) o[j] = 0.f;
        }
    }
}

extern "C" void kernel_launch(void* const* d_in, const int* in_sizes, int n_in,
                              void* d_out, int out_size) {
    (void)in_sizes; (void)n_in; (void)out_size;
    const float* cls = (const float*)d_in[0];
    const float* reg = (const float*)d_in[1];
    const float* anc = (const float*)d_in[2];
    float* out = (float*)d_out;

    k_prep<<<(NIMG * AN) / 256, 256>>>(cls, reg, anc);
    k_nms <<<NIMG * NCLS, 256>>>();
    k_topk<<<NIMG, 256>>>(out);
}

// round 6
// speedup vs baseline: 3.3840x; 1.6836x over previous
#include <cuda_runtime.h>
#include <cstdint>

#define NIMG 8
#define AN   16384
#define CN   21
#define NCLS 20
#define TOPK 100
#define NB   564            // buckets: (score_bits>>16) - 0x3D4C, scores in (0.05, 1)
#define BBASE 0x3D4Cu
#define THR_PROB 0.05f
#define THR_NMS  0.45f
#define CAP   8192          // per-(n,c) candidate capacity (actual ~4800, sigma ~42)
#define CAP2  1024          // per-chunk capacity
#define CHUNK 512

// -------- device scratch (no allocations allowed) --------
__device__ float4   g_boxes [NIMG * AN];
__device__ uint64_t g_cands [NIMG * NCLS * CAP];   // key = score_bits<<14 | (16383-anchor)
__device__ int      g_cnt   [NIMG * NCLS];          // zero-init; reset by k_nms each run
__device__ float    g_rows  [NIMG * NCLS * TOPK * 6];
__device__ int      g_counts[NIMG * NCLS];

// ---------------- stage 1: softmax + decode + direct candidate push ----------------
__global__ void __launch_bounds__(256) k_prep(const float* __restrict__ cls,
                                              const float* __restrict__ reg,
                                              const float* __restrict__ anc) {
    __shared__ float tile[8][672];   // 21 KB: per-warp staging of 32 anchors x 21 logits
    const unsigned FULL = 0xFFFFFFFFu;
    const int tid  = threadIdx.x;
    const int lane = tid & 31;
    const int wid  = tid >> 5;
    int t = blockIdx.x * blockDim.x + tid;           // grid exact: NIMG*AN threads
    int a = t & (AN - 1);
    int n = t >> 14;

    // coalesced float4 staging: 672 floats = 168 float4 per warp
    {
        const float4* src = (const float4*)(cls + (size_t)(t - lane) * CN);
        float4* dst = (float4*)tile[wid];
        #pragma unroll
        for (int i = 0; i < 5; i++) dst[lane + 32 * i] = src[lane + 32 * i];
        if (lane < 8) dst[lane + 160] = src[lane + 160];
        __syncwarp();
    }

    float x[CN];
    #pragma unroll
    for (int i = 0; i < CN; i++) x[i] = tile[wid][lane * CN + i];

    float mx = x[0];
    #pragma unroll
    for (int i = 1; i < CN; i++) mx = fmaxf(mx, x[i]);
    float e[CN];
    float sum = 0.f;
    #pragma unroll
    for (int i = 0; i < CN; i++) { e[i] = expf(x[i] - mx); sum += e[i]; }

    // pass 1: probabilities + per-class ballots; lane c-1 keeps ballot of class c
    unsigned myBal = 0;
    #pragma unroll
    for (int c = 1; c < CN; c++) {
        float p = __fdiv_rn(e[c], sum);
        e[c] = p;
        unsigned b = __ballot_sync(FULL, p > THR_PROB);
        if (lane == c - 1) myBal = b;
    }
    // single warp-wide atomic: lane c updates class-c counter (spread addrs, one latency)
    int basePos = 0;
    if (lane < NCLS) basePos = atomicAdd(&g_cnt[n * NCLS + lane], __popc(myBal));

    // pass 2: positions + key stores
    #pragma unroll
    for (int c = 1; c < CN; c++) {
        float p = e[c];
        bool pass = (p > THR_PROB);
        unsigned b = __ballot_sync(FULL, pass);
        int pos = __shfl_sync(FULL, basePos, c - 1);
        if (pass) {
            int my = pos + __popc(b & ((1u << lane) - 1));
            if (my < CAP)
                g_cands[(size_t)(n * NCLS + (c - 1)) * CAP + my] =
                    ((uint64_t)__float_as_uint(p) << 14) | (uint64_t)(16383 - a);
        }
    }

    float4 l   = ((const float4*)reg)[t];
    float4 an4 = ((const float4*)anc)[a];
    float cx = an4.x + l.x * 0.1f * an4.z;
    float cy = an4.y + l.y * 0.1f * an4.w;
    float w  = an4.z * expf(l.z * 0.2f);
    float h  = an4.w * expf(l.w * 0.2f);
    float hx = w * 0.5f, hy = h * 0.5f;
    float x1 = fminf(fmaxf(cx - hx, 0.f), 1.f);
    float y1 = fminf(fmaxf(cy - hy, 0.f), 1.f);
    float x2 = fminf(fmaxf(cx + hx, 0.f), 1.f);
    float y2 = fminf(fmaxf(cy + hy, 0.f), 1.f);
    g_boxes[t] = make_float4(x1, y1, x2, y2);
}

// IoU check with pre-hoisted areas; exact same op order as reference (IoU is symmetric:
// fmax/fmin/add are commutative, so operand order does not affect bits)
__device__ __forceinline__ bool iou_gt2(float4 p, float aP, float4 q, float aQ) {
    float ltx = fmaxf(p.x, q.x), lty = fmaxf(p.y, q.y);
    float rbx = fminf(p.z, q.z), rby = fminf(p.w, q.w);
    float iw = fmaxf(rbx - ltx, 0.f), ih = fmaxf(rby - lty, 0.f);
    float inter = iw * ih;
    float uni = aP + aQ - inter;
    float iou = (uni > 0.f) ? __fdiv_rn(inter, uni) : 0.f;
    return iou > THR_NMS;
}

// ---------------- stage 2: per-(image,class) threshold + small-sort greedy NMS ----------------
__global__ void __launch_bounds__(256) k_nms() {
    __shared__ uint64_t keys2[CAP2];          // 8 KB
    __shared__ uint32_t whist[8][576];        // 18 KB
    __shared__ uint32_t hist[577];
    __shared__ uint32_t sufc[577];            // sufc[b] = #cands in buckets >= b
    __shared__ float4   s_selbox[TOPK];
    __shared__ float    s_selA[TOPK];
    __shared__ float4   s_wbox[32];
    __shared__ float    s_wA[32];
    __shared__ uint64_t s_wkey[32];
    __shared__ uint32_t s_mask[32];           // intra-window kill masks
    __shared__ uint32_t s_supb;               // suppressed-by-selected bitmask
    __shared__ int s_blo, s_cnt2, s_selcnt;

    const unsigned FULL = 0xFFFFFFFFu;
    const int tid  = threadIdx.x;
    const int lane = tid & 31;
    const int wid  = tid >> 5;
    const int n    = blockIdx.x / NCLS;
    const int cc   = blockIdx.x % NCLS;
    const int nc   = n * NCLS + cc;
    const uint64_t* glist = g_cands + (size_t)nc * CAP;
    const float4*   boxN  = g_boxes + (size_t)n * AN;
    float* rowBase = g_rows + (size_t)nc * TOPK * 6;

    int cnt = g_cnt[nc];
    if (cnt > CAP) cnt = CAP;

    for (int i = tid; i < 8 * 576; i += 256) ((uint32_t*)whist)[i] = 0;
    if (tid == 0) s_selcnt = 0;
    __syncthreads();

    for (int i = tid; i < cnt; i += 256) {
        uint64_t key = glist[i];
        int b = (int)(uint32_t)(key >> 30) - (int)BBASE;
        atomicAdd(&whist[wid][b], 1u);
    }
    __syncthreads();

    for (int b = tid; b < 576; b += 256) {
        uint32_t s = 0;
        #pragma unroll
        for (int w = 0; w < 8; w++) s += whist[w][b];
        hist[b] = s;
    }
    __syncthreads();

    if (tid < 32) {
        int hi = 576 - 18 * lane;
        int lo = hi - 18;
        uint32_t sum = 0;
        #pragma unroll
        for (int b = 0; b < 18; b++) sum += hist[lo + b];
        uint32_t pre = sum;
        #pragma unroll
        for (int d = 1; d < 32; d <<= 1) {
            uint32_t v = __shfl_up_sync(FULL, pre, d);
            if (lane >= d) pre += v;
        }
        uint32_t run = pre - sum;
        for (int b = hi - 1; b >= lo; b--) { run += hist[b]; sufc[b] = run; }
        if (lane == 0) sufc[576] = 0;
    }
    __syncthreads();

    int b_hi = NB - 1;
    while (true) {
        if (tid == 0) {
            uint32_t target = sufc[b_hi + 1] + CHUNK;
            int blo = 0;
            if (sufc[0] >= target) {
                int lo2 = 0, hi2 = b_hi;
                while (lo2 < hi2) {
                    int mid = (lo2 + hi2 + 1) >> 1;
                    if (sufc[mid] >= target) lo2 = mid; else hi2 = mid - 1;
                }
                blo = lo2;
            }
            s_blo = blo;
            s_cnt2 = 0;
        }
        __syncthreads();
        const int blo = s_blo;

        for (int base = wid * 32; base < cnt; base += 256) {
            int i = base + lane;
            uint64_t key = 0ull;
            bool sel = false;
            if (i < cnt) {
                key = glist[i];
                int b = (int)(uint32_t)(key >> 30) - (int)BBASE;
                sel = (b >= blo) && (b <= b_hi);
            }
            unsigned bal = __ballot_sync(FULL, sel);
            if (bal) {
                int pos = 0;
                if (lane == 0) pos = atomicAdd(&s_cnt2, __popc(bal));
                pos = __shfl_sync(FULL, pos, 0);
                if (sel) {
                    int my = pos + __popc(bal & ((1u << lane) - 1));
                    if (my < CAP2) keys2[my] = key;
                }
            }
        }
        __syncthreads();
        int M = s_cnt2;
        if (M > CAP2) M = CAP2;

        int P = 32;
        while (P < M) P <<= 1;
        for (int i = M + tid; i < P; i += 256) keys2[i] = 0ull;
        __syncthreads();
        for (int k = 2; k <= P; k <<= 1)
            for (int j = k >> 1; j > 0; j >>= 1) {
                for (int i = tid; i < (P >> 1); i += 256) {
                    int pos = ((i & ~(j - 1)) << 1) | (i & (j - 1));
                    int par = pos | j;
                    uint64_t xv = keys2[pos], yv = keys2[par];
                    bool desc = ((pos & k) == 0);
                    if (desc ? (xv < yv) : (xv > yv)) { keys2[pos] = yv; keys2[par] = xv; }
                }
                __syncthreads();
            }

        // ---- block-parallel batch-32 greedy: exact sequential-greedy semantics ----
        for (int base = 0; base < M && s_selcnt < TOPK; base += 32) {
            const int m = min(32, M - base);

            // stage window: boxes, areas, keys, mask init
            if (tid < 32) {
                uint64_t key = (tid < m) ? keys2[base + tid] : 0ull;
                float4 b4 = make_float4(0.f, 0.f, 0.f, 0.f);
                if (tid < m) b4 = boxN[16383u - ((uint32_t)key & 0x3FFFu)];
                s_wkey[tid] = key;
                s_wbox[tid] = b4;
                s_wA[tid]   = (b4.z - b4.x) * (b4.w - b4.y);
                s_mask[tid] = 0;
                if (tid == 0) s_supb = (m < 32) ? ~((1u << m) - 1) : 0u;
            }
            __syncthreads();

            const int selcnt = s_selcnt;
            // phase A: suppression vs selected list (warp w strides selected idx by 8)
            {
                float4 myb = s_wbox[lane];
                float  myA = s_wA[lane];
                bool kill = false;
                if (lane < m)
                    for (int j = wid; j < selcnt; j += 8)
                        kill |= iou_gt2(s_selbox[j], s_selA[j], myb, myA);
                unsigned bal = __ballot_sync(FULL, kill);
                if (lane == 0 && bal) atomicOr(&s_supb, bal);
            }
            // phase A2: intra-window kill matrix, 496 pairs over 256 threads
            {
                int npair = m * (m - 1) / 2;
                for (int p = tid; p < npair; p += 256) {
                    int i = (int)((sqrtf((float)(8 * p + 1)) - 1.0f) * 0.5f);
                    while ((i + 1) * i / 2 <= p) i++;
                    while (i * (i - 1) / 2 > p) i--;
                    int j = p - i * (i - 1) / 2;     // j < i
                    if (iou_gt2(s_wbox[j], s_wA[j], s_wbox[i], s_wA[i]))
                        atomicOr(&s_mask[i], 1u << j);
                }
            }
            __syncthreads();

            // phase B: serial resolution (warp 0), pure ALU + ballots
            if (wid == 0) {
                unsigned killed = s_supb;
                unsigned mymask = s_mask[lane];
                unsigned selMask = 0;
                int space = TOPK - selcnt;
                for (int i = 0; i < m; i++) {
                    if (space == 0) break;
                    if (!((killed >> i) & 1)) {
                        selMask |= 1u << i;
                        space--;
                        killed |= __ballot_sync(FULL, (mymask >> i) & 1);
                    }
                }
                bool selme = (selMask >> lane) & 1;
                int rank = __popc(selMask & ((1u << lane) - 1));
                if (selme) {
                    int slot = selcnt + rank;
                    float4 b4 = s_wbox[lane];
                    s_selbox[slot] = b4;
                    s_selA[slot]   = s_wA[lane];
                    float* r = rowBase + slot * 6;
                    r[0] = b4.x; r[1] = b4.y; r[2] = b4.z; r[3] = b4.w;
                    r[4] = __uint_as_float((uint32_t)(s_wkey[lane] >> 14));
                    r[5] = (float)(cc + 1);
                }
                if (lane == 0) s_selcnt = selcnt + __popc(selMask);
            }
            __syncthreads();
        }

        if (s_selcnt >= TOPK || blo == 0) {
            if (tid == 0) { g_counts[nc] = s_selcnt; g_cnt[nc] = 0; }
            break;
        }
        b_hi = blo - 1;
    }
}

// ---------------- stage 3: per-image top-100 (lax.top_k semantics) ----------------
__global__ void __launch_bounds__(256) k_topk(float* __restrict__ out) {
    __shared__ uint64_t kb[2048];
    const int n = blockIdx.x, tid = threadIdx.x;

    for (int e = tid; e < 2048; e += 256) {
        uint64_t key = 0ull;
        if (e < NCLS * TOPK) {
            int c = e / TOPK, k = e % TOPK;
            if (k < g_counts[n * NCLS + c]) {
                float s = g_rows[(((size_t)(n * NCLS + c)) * TOPK + k) * 6 + 4];
                uint32_t flat = (uint32_t)((c + 1) * TOPK + k);
                key = ((uint64_t)__float_as_uint(s) << 32) | (uint64_t)(4095u - flat);
            }
        }
        kb[e] = key;
    }
    __syncthreads();

    for (int k = 2; k <= 2048; k <<= 1)
        for (int j = k >> 1; j > 0; j >>= 1) {
            for (int i = tid; i < 1024; i += 256) {
                int pos = ((i & ~(j - 1)) << 1) | (i & (j - 1));
                int par = pos | j;
                uint64_t xv = kb[pos], yv = kb[par];
                bool desc = ((pos & k) == 0);
                if (desc ? (xv < yv) : (xv > yv)) { kb[pos] = yv; kb[par] = xv; }
            }
            __syncthreads();
        }

    if (tid < TOPK) {
        uint64_t key = kb[tid];
        float* o = out + ((size_t)n * TOPK + tid) * 6;
        if ((key >> 32) != 0ull) {
            uint32_t flat = 4095u - (uint32_t)key;
            int c = (int)(flat / TOPK) - 1;
            int k = (int)(flat % TOPK);
            const float* r = g_rows + (((size_t)(n * NCLS + c)) * TOPK + k) * 6;
            #pragma unroll
            for (int j = 0; j < 6; j++) o[j] = r[j];
        } else {
            #pragma unroll
            for (int j = 0; j < 6; j++) o[j] = 0.f;
        }
    }
}

extern "C" void kernel_launch(void* const* d_in, const int* in_sizes, int n_in,
                              void* d_out, int out_size) {
    (void)in_sizes; (void)n_in; (void)out_size;
    const float* cls = (const float*)d_in[0];
    const float* reg = (const float*)d_in[1];
    const float* anc = (const float*)d_in[2];
    float* out = (float*)d_out;

    k_prep<<<(NIMG * AN) / 256, 256>>>(cls, reg, anc);
    k_nms <<<NIMG * NCLS, 256>>>();
    k_topk<<<NIMG, 256>>>(out);
}

// round 7
// speedup vs baseline: 4.1306x; 1.2206x over previous
#include <cuda_runtime.h>
#include <cstdint>

#define NIMG 8
#define AN   16384
#define CN   21
#define NCLS 20
#define TOPK 100
#define NB   564            // buckets: (score_bits>>16) - 0x3D4C, scores in (0.05, 1)
#define BBASE 0x3D4Cu
#define THR_PROB 0.05f
#define THR_NMS  0.45f
#define CAP   8192          // per-(n,c) candidate capacity (actual ~4800, sigma ~42)
#define CAP2  1024          // per-chunk capacity
#define CHUNK 512

// -------- device scratch (no allocations allowed) --------
__device__ float4   g_boxes [NIMG * AN];
__device__ uint64_t g_cands [NIMG * NCLS * CAP];   // key = score_bits<<14 | (16383-anchor)
__device__ int      g_cnt   [NIMG * NCLS];          // zero-init; reset by k_nms each run
__device__ float    g_rows  [NIMG * NCLS * TOPK * 6];
__device__ int      g_counts[NIMG * NCLS];

// ---------------- stage 1: softmax + decode + direct candidate push ----------------
__global__ void __launch_bounds__(256) k_prep(const float* __restrict__ cls,
                                              const float* __restrict__ reg,
                                              const float* __restrict__ anc) {
    __shared__ float tile[8][672];   // 21 KB: per-warp staging of 32 anchors x 21 logits
    const unsigned FULL = 0xFFFFFFFFu;
    const int tid  = threadIdx.x;
    const int lane = tid & 31;
    const int wid  = tid >> 5;
    int t = blockIdx.x * blockDim.x + tid;           // grid exact: NIMG*AN threads
    int a = t & (AN - 1);
    int n = t >> 14;

    // coalesced float4 staging: 672 floats = 168 float4 per warp
    {
        const float4* src = (const float4*)(cls + (size_t)(t - lane) * CN);
        float4* dst = (float4*)tile[wid];
        #pragma unroll
        for (int i = 0; i < 5; i++) dst[lane + 32 * i] = src[lane + 32 * i];
        if (lane < 8) dst[lane + 160] = src[lane + 160];
        __syncwarp();
    }

    float x[CN];
    #pragma unroll
    for (int i = 0; i < CN; i++) x[i] = tile[wid][lane * CN + i];

    float mx = x[0];
    #pragma unroll
    for (int i = 1; i < CN; i++) mx = fmaxf(mx, x[i]);
    float e[CN];
    float sum = 0.f;
    #pragma unroll
    for (int i = 0; i < CN; i++) { e[i] = expf(x[i] - mx); sum += e[i]; }

    // pass 1: probabilities + per-class ballots; lane c-1 keeps ballot of class c
    unsigned myBal = 0;
    #pragma unroll
    for (int c = 1; c < CN; c++) {
        float p = __fdiv_rn(e[c], sum);
        e[c] = p;
        unsigned b = __ballot_sync(FULL, p > THR_PROB);
        if (lane == c - 1) myBal = b;
    }
    // single warp-wide atomic: lane c updates class-c counter (spread addrs, one latency)
    int basePos = 0;
    if (lane < NCLS) basePos = atomicAdd(&g_cnt[n * NCLS + lane], __popc(myBal));

    // pass 2: positions + key stores (ballots reused via shfl, no re-vote)
    #pragma unroll
    for (int c = 1; c < CN; c++) {
        unsigned b = __shfl_sync(FULL, myBal, c - 1);
        int pos    = __shfl_sync(FULL, basePos, c - 1);
        if ((b >> lane) & 1) {
            int my = pos + __popc(b & ((1u << lane) - 1));
            if (my < CAP)
                g_cands[(size_t)(n * NCLS + (c - 1)) * CAP + my] =
                    ((uint64_t)__float_as_uint(e[c]) << 14) | (uint64_t)(16383 - a);
        }
    }

    float4 l   = ((const float4*)reg)[t];
    float4 an4 = ((const float4*)anc)[a];
    float cx = an4.x + l.x * 0.1f * an4.z;
    float cy = an4.y + l.y * 0.1f * an4.w;
    float w  = an4.z * expf(l.z * 0.2f);
    float h  = an4.w * expf(l.w * 0.2f);
    float hx = w * 0.5f, hy = h * 0.5f;
    float x1 = fminf(fmaxf(cx - hx, 0.f), 1.f);
    float y1 = fminf(fmaxf(cy - hy, 0.f), 1.f);
    float x2 = fminf(fmaxf(cx + hx, 0.f), 1.f);
    float y2 = fminf(fmaxf(cy + hy, 0.f), 1.f);
    g_boxes[t] = make_float4(x1, y1, x2, y2);
}

// IoU check with pre-hoisted areas; exact same op order as reference (IoU is symmetric:
// fmax/fmin/add are commutative, so operand order does not affect bits)
__device__ __forceinline__ bool iou_gt2(float4 p, float aP, float4 q, float aQ) {
    float ltx = fmaxf(p.x, q.x), lty = fmaxf(p.y, q.y);
    float rbx = fminf(p.z, q.z), rby = fminf(p.w, q.w);
    float iw = fmaxf(rbx - ltx, 0.f), ih = fmaxf(rby - lty, 0.f);
    float inter = iw * ih;
    float uni = aP + aQ - inter;
    float iou = (uni > 0.f) ? __fdiv_rn(inter, uni) : 0.f;
    return iou > THR_NMS;
}

// ---------------- stage 2: per-(image,class) threshold + small-sort greedy NMS ----------------
__global__ void __launch_bounds__(256) k_nms() {
    __shared__ uint64_t keys2[CAP2];          // 8 KB
    __shared__ float4   s_cbox[CAP2];         // 16 KB: prefetched chunk boxes
    __shared__ float    s_cA[CAP2];           // 4 KB: chunk areas
    __shared__ uint32_t whist[4][576];        // 9 KB
    __shared__ uint32_t hist[577];
    __shared__ uint32_t sufc[577];            // sufc[b] = #cands in buckets >= b
    __shared__ float4   s_selbox[TOPK];
    __shared__ float    s_selA[TOPK];
    __shared__ uint32_t s_mask[32];           // intra-window kill masks
    __shared__ uint32_t s_supb;               // suppressed-by-selected bitmask
    __shared__ int s_blo, s_cnt2, s_selcnt;

    const unsigned FULL = 0xFFFFFFFFu;
    const int tid  = threadIdx.x;
    const int lane = tid & 31;
    const int wid  = tid >> 5;
    const int n    = blockIdx.x / NCLS;
    const int cc   = blockIdx.x % NCLS;
    const int nc   = n * NCLS + cc;
    const uint64_t* glist = g_cands + (size_t)nc * CAP;
    const float4*   boxN  = g_boxes + (size_t)n * AN;
    float* rowBase = g_rows + (size_t)nc * TOPK * 6;

    int cnt = g_cnt[nc];
    if (cnt > CAP) cnt = CAP;

    for (int i = tid; i < 4 * 576; i += 256) ((uint32_t*)whist)[i] = 0;
    if (tid == 0) s_selcnt = 0;
    __syncthreads();

    for (int i = tid; i < cnt; i += 256) {
        uint64_t key = glist[i];
        int b = (int)(uint32_t)(key >> 30) - (int)BBASE;
        atomicAdd(&whist[wid & 3][b], 1u);
    }
    __syncthreads();

    for (int b = tid; b < 576; b += 256) {
        uint32_t s = 0;
        #pragma unroll
        for (int w = 0; w < 4; w++) s += whist[w][b];
        hist[b] = s;
    }
    __syncthreads();

    if (tid < 32) {
        int hi = 576 - 18 * lane;
        int lo = hi - 18;
        uint32_t sum = 0;
        #pragma unroll
        for (int b = 0; b < 18; b++) sum += hist[lo + b];
        uint32_t pre = sum;
        #pragma unroll
        for (int d = 1; d < 32; d <<= 1) {
            uint32_t v = __shfl_up_sync(FULL, pre, d);
            if (lane >= d) pre += v;
        }
        uint32_t run = pre - sum;
        for (int b = hi - 1; b >= lo; b--) { run += hist[b]; sufc[b] = run; }
        if (lane == 0) sufc[576] = 0;
    }
    __syncthreads();

    int b_hi = NB - 1;
    while (true) {
        if (tid == 0) {
            uint32_t target = sufc[b_hi + 1] + CHUNK;
            int blo = 0;
            if (sufc[0] >= target) {
                int lo2 = 0, hi2 = b_hi;
                while (lo2 < hi2) {
                    int mid = (lo2 + hi2 + 1) >> 1;
                    if (sufc[mid] >= target) lo2 = mid; else hi2 = mid - 1;
                }
                blo = lo2;
            }
            s_blo = blo;
            s_cnt2 = 0;
        }
        __syncthreads();
        const int blo = s_blo;

        for (int base = wid * 32; base < cnt; base += 256) {
            int i = base + lane;
            uint64_t key = 0ull;
            bool sel = false;
            if (i < cnt) {
                key = glist[i];
                int b = (int)(uint32_t)(key >> 30) - (int)BBASE;
                sel = (b >= blo) && (b <= b_hi);
            }
            unsigned bal = __ballot_sync(FULL, sel);
            if (bal) {
                int pos = 0;
                if (lane == 0) pos = atomicAdd(&s_cnt2, __popc(bal));
                pos = __shfl_sync(FULL, pos, 0);
                if (sel) {
                    int my = pos + __popc(bal & ((1u << lane) - 1));
                    if (my < CAP2) keys2[my] = key;
                }
            }
        }
        __syncthreads();
        int M = s_cnt2;
        if (M > CAP2) M = CAP2;

        int P = 32;
        while (P < M) P <<= 1;
        for (int i = M + tid; i < P; i += 256) keys2[i] = 0ull;
        __syncthreads();
        for (int k = 2; k <= P; k <<= 1)
            for (int j = k >> 1; j > 0; j >>= 1) {
                for (int i = tid; i < (P >> 1); i += 256) {
                    int pos = ((i & ~(j - 1)) << 1) | (i & (j - 1));
                    int par = pos | j;
                    uint64_t xv = keys2[pos], yv = keys2[par];
                    bool desc = ((pos & k) == 0);
                    if (desc ? (xv < yv) : (xv > yv)) { keys2[pos] = yv; keys2[par] = xv; }
                }
                __syncthreads();
            }

        // chunk-wide box prefetch: one exposed gather, high MLP
        for (int i = tid; i < M; i += 256) {
            uint64_t key = keys2[i];
            float4 b4 = boxN[16383u - ((uint32_t)key & 0x3FFFu)];
            s_cbox[i] = b4;
            s_cA[i]   = (b4.z - b4.x) * (b4.w - b4.y);
        }
        __syncthreads();

        // ---- block-parallel batch-32 greedy: exact sequential-greedy semantics ----
        for (int base = 0; base < M && s_selcnt < TOPK; base += 32) {
            const int m = min(32, M - base);

            if (tid < 32) {
                s_mask[tid] = 0;
                if (tid == 0) s_supb = (m < 32) ? ~((1u << m) - 1) : 0u;
            }
            __syncthreads();

            const int selcnt = s_selcnt;
            // phase A: suppression vs selected list (warp w strides selected idx by 8)
            {
                int ci = base + ((lane < m) ? lane : 0);
                float4 myb = s_cbox[ci];
                float  myA = s_cA[ci];
                bool kill = false;
                if (lane < m) {
                    #pragma unroll 4
                    for (int j = wid; j < selcnt; j += 8)
                        kill |= iou_gt2(s_selbox[j], s_selA[j], myb, myA);
                }
                unsigned bal = __ballot_sync(FULL, kill);
                if (lane == 0 && bal) atomicOr(&s_supb, bal);
            }
            // phase A2: intra-window kill matrix, <=496 pairs over 256 threads
            {
                int npair = m * (m - 1) / 2;
                for (int p = tid; p < npair; p += 256) {
                    int i = (int)((sqrtf((float)(8 * p + 1)) - 1.0f) * 0.5f);
                    while ((i + 1) * i / 2 <= p) i++;
                    while (i * (i - 1) / 2 > p) i--;
                    int j = p - i * (i - 1) / 2;     // j < i
                    if (iou_gt2(s_cbox[base + j], s_cA[base + j],
                                s_cbox[base + i], s_cA[base + i]))
                        atomicOr(&s_mask[i], 1u << j);
                }
            }
            __syncthreads();

            // phase B: serial resolution (warp 0), pure ALU + ballots
            if (wid == 0) {
                unsigned killed = s_supb;
                unsigned mymask = s_mask[lane];
                unsigned selMask = 0;
                int space = TOPK - selcnt;
                for (int i = 0; i < m; i++) {
                    if (space == 0) break;
                    if (!((killed >> i) & 1)) {
                        selMask |= 1u << i;
                        space--;
                        killed |= __ballot_sync(FULL, (mymask >> i) & 1);
                    }
                }
                bool selme = (selMask >> lane) & 1;
                int rank = __popc(selMask & ((1u << lane) - 1));
                if (selme) {
                    int slot = selcnt + rank;
                    float4 b4 = s_cbox[base + lane];
                    s_selbox[slot] = b4;
                    s_selA[slot]   = s_cA[base + lane];
                    float* r = rowBase + slot * 6;
                    r[0] = b4.x; r[1] = b4.y; r[2] = b4.z; r[3] = b4.w;
                    r[4] = __uint_as_float((uint32_t)(keys2[base + lane] >> 14));
                    r[5] = (float)(cc + 1);
                }
                if (lane == 0) s_selcnt = selcnt + __popc(selMask);
            }
            __syncthreads();
        }

        if (s_selcnt >= TOPK || blo == 0) {
            if (tid == 0) { g_counts[nc] = s_selcnt; g_cnt[nc] = 0; }
            break;
        }
        b_hi = blo - 1;
    }
}

// ---------------- stage 3: per-image top-100 via bucket cutoff (lax.top_k semantics) ----------------
__global__ void __launch_bounds__(256) k_topk(float* __restrict__ out) {
    __shared__ uint64_t kb[NCLS * TOPK];      // 16 KB: all candidate keys
    __shared__ uint64_t keys2[2048];          // 16 KB: compacted (worst-case all)
    __shared__ uint32_t hist[577];
    __shared__ uint32_t sufc[577];
    __shared__ int s_cnts[NCLS];
    __shared__ int s_bcut, s_m2;

    const unsigned FULL = 0xFFFFFFFFu;
    const int n = blockIdx.x, tid = threadIdx.x;
    const int lane = tid & 31;

    if (tid < NCLS) s_cnts[tid] = g_counts[n * NCLS + tid];
    for (int i = tid; i < 577; i += 256) hist[i] = 0;
    __syncthreads();

    // build keys + histogram by score bucket
    for (int e = tid; e < NCLS * TOPK; e += 256) {
        int c = e / TOPK, k = e % TOPK;
        uint64_t key = 0ull;
        if (k < s_cnts[c]) {
            uint32_t sb = __float_as_uint(
                g_rows[(((size_t)(n * NCLS + c)) * TOPK + k) * 6 + 4]);
            uint32_t flat = (uint32_t)((c + 1) * TOPK + k);
            key = ((uint64_t)sb << 32) | (uint64_t)(4095u - flat);
            atomicAdd(&hist[(sb >> 16) - BBASE], 1u);
        }
        kb[e] = key;
    }
    __syncthreads();

    // suffix sums (warp 0)
    if (tid < 32) {
        int hi = 576 - 18 * lane;
        int lo = hi - 18;
        uint32_t sum = 0;
        #pragma unroll
        for (int b = 0; b < 18; b++) sum += hist[lo + b];
        uint32_t pre = sum;
        #pragma unroll
        for (int d = 1; d < 32; d <<= 1) {
            uint32_t v = __shfl_up_sync(FULL, pre, d);
            if (lane >= d) pre += v;
        }
        uint32_t run = pre - sum;
        for (int b = hi - 1; b >= lo; b--) { run += hist[b]; sufc[b] = run; }
    }
    __syncthreads();

    // cutoff bucket: largest b with sufc[b] >= min(TOPK, total)
    if (tid == 0) {
        uint32_t total = sufc[0];
        uint32_t target = total < TOPK ? total : TOPK;
        int bcut = 576;      // empty -> compact nothing
        if (target > 0) {
            int lo2 = 0, hi2 = 575;
            while (lo2 < hi2) {
                int mid = (lo2 + hi2 + 1) >> 1;
                if (sufc[mid] >= target) lo2 = mid; else hi2 = mid - 1;
            }
            bcut = lo2;
        }
        s_bcut = bcut;
        s_m2 = 0;
    }
    __syncthreads();
    const int bcut = s_bcut;

    // compact keys with bucket >= bcut
    for (int e = (tid >> 5) * 32; e < NCLS * TOPK; e += 256) {
        int i = e + lane;
        uint64_t key = (i < NCLS * TOPK) ? kb[i] : 0ull;
        bool sel = key != 0ull && ((int)(uint32_t)(key >> 48) - (int)BBASE) >= bcut;
        unsigned bal = __ballot_sync(FULL, sel);
        if (bal) {
            int pos = 0;
            if (lane == 0) pos = atomicAdd(&s_m2, __popc(bal));
            pos = __shfl_sync(FULL, pos, 0);
            if (sel) keys2[pos + __popc(bal & ((1u << lane) - 1))] = key;
        }
    }
    __syncthreads();
    int M2 = s_m2;

    // pad + small bitonic sort descending (P typically 128)
    int P = 32;
    while (P < M2) P <<= 1;
    for (int i = M2 + tid; i < P; i += 256) keys2[i] = 0ull;
    __syncthreads();
    for (int k = 2; k <= P; k <<= 1)
        for (int j = k >> 1; j > 0; j >>= 1) {
            for (int i = tid; i < (P >> 1); i += 256) {
                int pos = ((i & ~(j - 1)) << 1) | (i & (j - 1));
                int par = pos | j;
                uint64_t xv = keys2[pos], yv = keys2[par];
                bool desc = ((pos & k) == 0);
                if (desc ? (xv < yv) : (xv > yv)) { keys2[pos] = yv; keys2[par] = xv; }
            }
            __syncthreads();
        }

    if (tid < TOPK) {
        float* o = out + ((size_t)n * TOPK + tid) * 6;
        uint64_t key = (tid < M2) ? keys2[tid] : 0ull;
        if (key != 0ull) {
            uint32_t flat = 4095u - (uint32_t)key;
            int c = (int)(flat / TOPK) - 1;
            int k = (int)(flat % TOPK);
            const float* r = g_rows + (((size_t)(n * NCLS + c)) * TOPK + k) * 6;
            #pragma unroll
            for (int j = 0; j < 6; j++) o[j] = r[j];
        } else {
            #pragma unroll
            for (int j = 0; j < 6; j++) o[j] = 0.f;
        }
    }
}

extern "C" void kernel_launch(void* const* d_in, const int* in_sizes, int n_in,
                              void* d_out, int out_size) {
    (void)in_sizes; (void)n_in; (void)out_size;
    const float* cls = (const float*)d_in[0];
    const float* reg = (const float*)d_in[1];
    const float* anc = (const float*)d_in[2];
    float* out = (float*)d_out;

    k_prep<<<(NIMG * AN) / 256, 256>>>(cls, reg, anc);
    k_nms <<<NIMG * NCLS, 256>>>();
    k_topk<<<NIMG, 256>>>(out);
}